// round 11
// baseline (speedup 1.0000x reference)
#include <cuda_runtime.h>
#include <cuda_bf16.h>
#include <cstdint>

// Problem constants (fixed by the dataset)
#define BB 512      // batch
#define TT 512      // timesteps
#define II 128      // sensory inputs
#define UU 64       // LTC units
#define OO 15       // outputs
#define NUNF 4      // ode unfolds
#define LTC_EPS 1e-8f

// ---------------- device scratch (allocation-free rule: __device__ globals) ---------
__device__ float4 g_sparam[II * UU];     // sensory per-synapse {a, b, ce, c}
__device__ float4 g_rparam[UU * UU];     // recurrent per-synapse {a, b, ce, c}
__device__ float  g_sKn[UU], g_sKd[UU];  // sensory constant sums
__device__ float  g_cmt[UU], g_numbase[UU], g_denbase[UU];
__device__ float2 g_wns[BB * TT * UU];   // (w_num_s, w_den_s) per (b,t,u)  ~134MB

// ---------------- helpers ------------------------------------------------------------
// Two tanh for one MUFU op: pack two f32 args into f16x2, tanh.approx.f16x2, unpack.
__device__ __forceinline__ void tanh2_fast(float ax, float ay, float& tx, float& ty) {
    uint32_t h, r;
    asm("cvt.rn.f16x2.f32 %0, %1, %2;" : "=r"(h) : "f"(ay), "f"(ax));
    asm("tanh.approx.f16x2 %0, %1;" : "=r"(r) : "r"(h));
    asm("{\n\t"
        ".reg .b16 lo, hi;\n\t"
        "mov.b32 {lo, hi}, %2;\n\t"
        "cvt.f32.f16 %0, lo;\n\t"
        "cvt.f32.f16 %1, hi;\n\t"
        "}" : "=f"(tx), "=f"(ty) : "r"(r));
}
__device__ __forceinline__ float softplus_f(float x) {
    return log1pf(expf(x));
}

// ---------------- kernel 0a: fold parameters (one thread per synapse) -----------------
// sigmoid(z) = 0.5*tanh(z/2)+0.5; a = 0.5*sigma*iw, b = 0.5*sigma*(ib-mu),
// c = 0.5*sp(w), ce = c*erev (erev = +-1 so c == |ce|).
__global__ void fold_params_kernel(
    const float* __restrict__ iw, const float* __restrict__ ib,
    const float* __restrict__ sw, const float* __restrict__ smu,
    const float* __restrict__ ssig, const float* __restrict__ serev,
    const float* __restrict__ w, const float* __restrict__ mu,
    const float* __restrict__ sig, const float* __restrict__ erev)
{
    int idx = blockIdx.x * blockDim.x + threadIdx.x;
    if (idx < II * UU) {
        int i = idx / UU;
        float c  = 0.5f * softplus_f(sw[idx]);
        float ce = c * serev[idx];
        float a  = 0.5f * ssig[idx] * iw[i];
        float b  = 0.5f * ssig[idx] * (ib[i] - smu[idx]);
        g_sparam[idx] = make_float4(a, b, ce, c);
    }
    int r = idx - II * UU;
    if (r >= 0 && r < UU * UU) {
        float c  = 0.5f * softplus_f(w[r]);
        float ce = c * erev[r];
        float a  = 0.5f * sig[r];
        float b  = -0.5f * sig[r] * mu[r];
        g_rparam[r] = make_float4(a, b, ce, c);
    }
}

// ---------------- kernel 0b: per-neuron constant sums (parallel, 256 threads) ---------
__global__ void fold_neuron_kernel(
    const float* __restrict__ gleak, const float* __restrict__ vleak,
    const float* __restrict__ cm)
{
    __shared__ float part[4][4][UU];
    const int tid = threadIdx.x;
    const int u = tid & 63;
    const int g = tid >> 6;

    float skn = 0.f, skd = 0.f;
#pragma unroll 4
    for (int i = g * 32; i < g * 32 + 32; i++) {
        float4 p = g_sparam[i * UU + u];
        skn += p.z; skd += p.w;
    }
    float rkn = 0.f, rkd = 0.f;
#pragma unroll 4
    for (int j = g * 16; j < g * 16 + 16; j++) {
        float4 p = g_rparam[j * UU + u];
        rkn += p.z; rkd += p.w;
    }
    part[g][0][u] = skn; part[g][1][u] = skd;
    part[g][2][u] = rkn; part[g][3][u] = rkd;
    __syncthreads();
    if (g == 0) {
        skn = part[0][0][u] + part[1][0][u] + part[2][0][u] + part[3][0][u];
        skd = part[0][1][u] + part[1][1][u] + part[2][1][u] + part[3][1][u];
        rkn = part[0][2][u] + part[1][2][u] + part[2][2][u] + part[3][2][u];
        rkd = part[0][3][u] + part[1][3][u] + part[2][3][u] + part[3][3][u];
        g_sKn[u] = skn;
        g_sKd[u] = skd;
        float gp  = softplus_f(gleak[u]);
        float cmt = (float)NUNF * softplus_f(cm[u]);
        g_cmt[u]     = cmt;
        g_numbase[u] = gp * vleak[u] + rkn;
        g_denbase[u] = cmt + gp + rkd + LTC_EPS;
    }
}

// ---------------- kernel 1: sensory synapse sums over all (b,t) ----------------------
// Barrier-free, no smem (proven R8 version). 512 threads: u = tid>>3, ig = tid&7.
// Two rows per iteration; the (row0,row1) tanh pair shares one tanh.approx.f16x2.
#define ROWS_PER_BLOCK 128
__global__ __launch_bounds__(512, 1) void sensory_kernel(const float* __restrict__ x)
{
    const int tid = threadIdx.x;
    const int u  = tid >> 3;
    const int ig = tid & 7;

    float pa[16], pb[16], pce[16];
#pragma unroll
    for (int ii = 0; ii < 16; ii++) {
        float4 p = g_sparam[(ig * 16 + ii) * UU + u];
        pa[ii] = p.x; pb[ii] = p.y; pce[ii] = p.z;
    }
    const float kn = g_sKn[u];
    const float kd = g_sKd[u];

    const size_t base_row = (size_t)blockIdx.x * ROWS_PER_BLOCK;
    const float4* __restrict__ xr = (const float4*)x + base_row * (II / 4) + ig * 4;

    for (int r = 0; r < ROWS_PER_BLOCK; r += 2) {
        float4 x0[4], x1[4];
#pragma unroll
        for (int q = 0; q < 4; q++) {
            x0[q] = xr[(size_t)r * (II / 4) + q];
            x1[q] = xr[(size_t)(r + 1) * (II / 4) + q];
        }

        float pn0 = 0.f, pd0 = 0.f, pn1 = 0.f, pd1 = 0.f;
#pragma unroll
        for (int q = 0; q < 4; q++) {
            const int s = q * 4;
            const float xv0[4] = {x0[q].x, x0[q].y, x0[q].z, x0[q].w};
            const float xv1[4] = {x1[q].x, x1[q].y, x1[q].z, x1[q].w};
#pragma unroll
            for (int e = 0; e < 4; e++) {
                float a0 = fmaf(pa[s + e], xv0[e], pb[s + e]);
                float a1 = fmaf(pa[s + e], xv1[e], pb[s + e]);
                float t0, t1;
                tanh2_fast(a0, a1, t0, t1);
                float ce = pce[s + e];
                float c  = fabsf(ce);
                pn0 = fmaf(ce, t0, pn0);  pd0 = fmaf(c, t0, pd0);
                pn1 = fmaf(ce, t1, pn1);  pd1 = fmaf(c, t1, pd1);
            }
        }
#pragma unroll
        for (int o = 1; o <= 4; o <<= 1) {
            pn0 += __shfl_xor_sync(0xffffffffu, pn0, o);
            pn1 += __shfl_xor_sync(0xffffffffu, pn1, o);
            pd0 += __shfl_xor_sync(0xffffffffu, pd0, o);
            pd1 += __shfl_xor_sync(0xffffffffu, pd1, o);
        }
        if (ig == 0) {
            __stcg(&g_wns[(base_row + r) * UU + u],     make_float2(pn0 + kn, pd0 + kd));
            __stcg(&g_wns[(base_row + r + 1) * UU + u], make_float2(pn1 + kn, pd1 + kd));
        }
    }
}

// ---------------- kernel 2: sequential scan + LayerNorm + FC head --------------------
// grid=512 (ONE batch per block), block=128 (4 warps). Thread (u=tid>>1, half=tid&1)
// owns 32 of unit u's synapses in registers (96 regs). f16x2 tanh pairs ADJACENT
// synapses (same batch) -> 16 MUFU/thread/unfold. __launch_bounds__(128,3) caps regs
// at 170 so 3 blocks (3 independent barrier domains) actually co-reside per SM ->
// ~3.5 warps/SMSP hide each other's per-unfold tails.
__global__ __launch_bounds__(128, 3) void scan_kernel(
    const float* __restrict__ outw, const float* __restrict__ outb,
    const float* __restrict__ lnw,  const float* __restrict__ lnb,
    const float* __restrict__ fcw,  const float* __restrict__ fcb,
    float* __restrict__ out)
{
    __shared__ alignas(16) float vsm[2][UU];   // [buffer][unit]
    __shared__ float hbuf[UU];
    __shared__ float stats[2];

    const int tid  = threadIdx.x;
    const int u    = tid >> 1;          // 0..63
    const int half = tid & 1;           // which 32 synapses of unit u
    const int b    = blockIdx.x;

    float pa[32], pb[32], pce[32];
#pragma unroll
    for (int j = 0; j < 32; j++) {
        float4 p = g_rparam[(half * 32 + j) * UU + u];
        pa[j] = p.x; pb[j] = p.y; pce[j] = p.z;
    }
    const float cmtu = g_cmt[u];
    const float nb   = g_numbase[u];
    const float db   = g_denbase[u];

    if (half == 0) vsm[0][u] = 0.f;
    float vu = 0.f;
    __syncthreads();

    const float2* __restrict__ wns = g_wns + (size_t)b * TT * UU;
    float2 wnd = __ldcg(&wns[u]);

    for (int t = 0; t < TT; t++) {
        float2 wnd_n = (t + 1 < TT) ? __ldcg(&wns[(t + 1) * UU + u])
                                    : make_float2(0.f, 0.f);
#pragma unroll
        for (int k = 0; k < NUNF; k++) {
            const int cur = k & 1, nxt = cur ^ 1;
            const float4* vr4 = (const float4*)(vsm[cur]) + half * 8;

            // two accumulator chain pairs for ILP
            float pnE = 0.f, pdE = 0.f, pnO = 0.f, pdO = 0.f;
#pragma unroll
            for (int q = 0; q < 8; q++) {
                float4 v4 = vr4[q];
                const int s = q * 4;
                // pair (s, s+1)
                float a0 = fmaf(pa[s + 0], v4.x, pb[s + 0]);
                float a1 = fmaf(pa[s + 1], v4.y, pb[s + 1]);
                float t0, t1;
                tanh2_fast(a0, a1, t0, t1);
                pnE = fmaf(pce[s + 0], t0, pnE);  pdE = fmaf(fabsf(pce[s + 0]), t0, pdE);
                pnO = fmaf(pce[s + 1], t1, pnO);  pdO = fmaf(fabsf(pce[s + 1]), t1, pdO);
                // pair (s+2, s+3)
                float a2 = fmaf(pa[s + 2], v4.z, pb[s + 2]);
                float a3 = fmaf(pa[s + 3], v4.w, pb[s + 3]);
                float t2, t3;
                tanh2_fast(a2, a3, t2, t3);
                pnE = fmaf(pce[s + 2], t2, pnE);  pdE = fmaf(fabsf(pce[s + 2]), t2, pdE);
                pnO = fmaf(pce[s + 3], t3, pnO);  pdO = fmaf(fabsf(pce[s + 3]), t3, pdO);
            }
            float pn = pnE + pnO;
            float pd = pdE + pdO;
            pn += __shfl_xor_sync(0xffffffffu, pn, 1);
            pd += __shfl_xor_sync(0xffffffffu, pd, 1);

            vu = __fdividef(fmaf(cmtu, vu, nb) + wnd.x + pn, db + wnd.y + pd);
            if (half == 0) vsm[nxt][u] = vu;
            __syncthreads();
        }
        wnd = wnd_n;
    }

    // ----- head: h = v*ow + ob; LayerNorm(eps=1e-5); out = h @ fc_w^T + fc_b -----
    float h = fmaf(vu, outw[u], outb[u]);
    if (half == 0) hbuf[u] = h;
    __syncthreads();
    if (tid < 32) {
        float h0 = hbuf[tid], h1 = hbuf[tid + 32];
        float a = h0 + h1;
        float q = h0 * h0 + h1 * h1;
#pragma unroll
        for (int o = 16; o > 0; o >>= 1) {
            a += __shfl_down_sync(0xffffffffu, a, o);
            q += __shfl_down_sync(0xffffffffu, q, o);
        }
        if (tid == 0) {
            float mean = a * (1.0f / UU);
            float var  = q * (1.0f / UU) - mean * mean;
            stats[0] = mean;
            stats[1] = rsqrtf(var + 1e-5f);
        }
    }
    __syncthreads();
    if (half == 0)
        hbuf[u] = fmaf((h - stats[0]) * stats[1], lnw[u], lnb[u]);
    __syncthreads();
    if (tid < OO) {
        float acc = fcb[tid];
#pragma unroll
        for (int uu = 0; uu < UU; uu++)
            acc = fmaf(hbuf[uu], fcw[tid * UU + uu], acc);
        out[b * OO + tid] = acc;
    }
}

// ---------------- launch --------------------------------------------------------------
extern "C" void kernel_launch(void* const* d_in, const int* in_sizes, int n_in,
                              void* d_out, int out_size)
{
    const float* x     = (const float*)d_in[0];
    const float* iw    = (const float*)d_in[1];
    const float* ibv   = (const float*)d_in[2];
    const float* sw    = (const float*)d_in[3];
    const float* smu   = (const float*)d_in[4];
    const float* ssig  = (const float*)d_in[5];
    const float* serev = (const float*)d_in[6];
    const float* w     = (const float*)d_in[7];
    const float* mu    = (const float*)d_in[8];
    const float* sig   = (const float*)d_in[9];
    const float* erev  = (const float*)d_in[10];
    const float* gleak = (const float*)d_in[11];
    const float* vleak = (const float*)d_in[12];
    const float* cm    = (const float*)d_in[13];
    const float* outw  = (const float*)d_in[14];
    const float* outb  = (const float*)d_in[15];
    const float* lnw   = (const float*)d_in[16];
    const float* lnb   = (const float*)d_in[17];
    const float* fcw   = (const float*)d_in[18];
    const float* fcb   = (const float*)d_in[19];
    float* out = (float*)d_out;

    const int n_syn = II * UU + UU * UU;           // 12288
    fold_params_kernel<<<(n_syn + 255) / 256, 256>>>(iw, ibv, sw, smu, ssig, serev,
                                                     w, mu, sig, erev);
    fold_neuron_kernel<<<1, 256>>>(gleak, vleak, cm);

    int nblocks = (BB * TT) / ROWS_PER_BLOCK;      // 2048
    sensory_kernel<<<nblocks, 512>>>(x);

    scan_kernel<<<BB, 128>>>(outw, outb, lnw, lnb, fcw, fcb, out);
}